// round 2
// baseline (speedup 1.0000x reference)
#include <cuda_runtime.h>
#include <math.h>

// ---------------------------------------------------------------------------
// NTM read head, B=16384, CTRL=512, N=128, M=64, 70 controller outputs.
// Kernel 1: o = emb @ W^T + b  (fp32 GEMM, packed f32x2 FMA) + activations.
// Kernel 2: per-batch addressing (cos sim, softmax, interp, shift, sharpen)
//           + weighted read, memory tile staged in SMEM (single HBM read).
// ---------------------------------------------------------------------------

#define MAXB 16384
typedef unsigned long long ull;

// Scratch (allocation-free rule: __device__ globals)
__device__ float g_kbuf[MAXB * 64];  // k vectors
__device__ float g_pbuf[MAXB * 8];   // beta, g, s0, s1, s2, gamma

__device__ __forceinline__ float softplusf(float x) {
    return (x > 20.0f) ? x : log1pf(expf(x));
}
__device__ __forceinline__ float lo32(ull v) {
    return __uint_as_float((unsigned)(v & 0xffffffffu));
}
__device__ __forceinline__ float hi32(ull v) {
    return __uint_as_float((unsigned)(v >> 32));
}

// ---------------------------------------------------------------------------
// Kernel 1: GEMM [B,512] x [512,70]^T, BM=64, BN=80 (70 padded), BK=16.
// 256 threads as 16x16; thread tile 4 rows x 5 cols, rows paired in f32x2.
// ---------------------------------------------------------------------------
__global__ __launch_bounds__(256) void ntm_gemm_kernel(
    const float* __restrict__ emb, const float* __restrict__ Wm,
    const float* __restrict__ bias, int B)
{
    __shared__ __align__(16) float  embS[16][68];   // [k][row], stride 68 (LDS.64-clean)
    __shared__ __align__(16) float2 wS2[16][80];    // [k][col], duplicated {w,w}

    const int t  = threadIdx.x;
    const int tx = t & 15;    // col group -> cols tx*5 .. tx*5+4
    const int ty = t >> 4;    // row group -> rows ty*4 .. ty*4+3
    const int rb = blockIdx.x * 64;

    ull acc01[5], acc23[5];   // rows (ty*4, ty*4+1) and (ty*4+2, ty*4+3)
    #pragma unroll
    for (int j = 0; j < 5; j++) { acc01[j] = 0ull; acc23[j] = 0ull; }

    const int lrow = t >> 2;  // 0..63
    const int lkq  = t & 3;   // 0..3
    const int grow = (rb + lrow < B) ? (rb + lrow) : (B - 1);

    const int c0 = t >> 2;          // 0..63
    const int q0 = t & 3;
    const int i1 = t + 256;         // 256..511 -> valid if < 320
    const int c1 = i1 >> 2;         // 64..79
    const int q1 = i1 & 3;
    const bool has1 = (i1 < 320);

    for (int kk = 0; kk < 512; kk += 16) {
        // prefetch gmem -> regs
        float4 ev = *(const float4*)(emb + (size_t)grow * 512 + kk + lkq * 4);
        float4 wv0 = make_float4(0.f, 0.f, 0.f, 0.f);
        float4 wv1 = make_float4(0.f, 0.f, 0.f, 0.f);
        if (c0 < 70) wv0 = *(const float4*)(Wm + (size_t)c0 * 512 + kk + q0 * 4);
        if (has1 && c1 < 70) wv1 = *(const float4*)(Wm + (size_t)c1 * 512 + kk + q1 * 4);

        __syncthreads();  // previous iteration's smem reads complete

        embS[lkq*4+0][lrow] = ev.x; embS[lkq*4+1][lrow] = ev.y;
        embS[lkq*4+2][lrow] = ev.z; embS[lkq*4+3][lrow] = ev.w;
        wS2[q0*4+0][c0] = make_float2(wv0.x, wv0.x);
        wS2[q0*4+1][c0] = make_float2(wv0.y, wv0.y);
        wS2[q0*4+2][c0] = make_float2(wv0.z, wv0.z);
        wS2[q0*4+3][c0] = make_float2(wv0.w, wv0.w);
        if (has1) {
            wS2[q1*4+0][c1] = make_float2(wv1.x, wv1.x);
            wS2[q1*4+1][c1] = make_float2(wv1.y, wv1.y);
            wS2[q1*4+2][c1] = make_float2(wv1.z, wv1.z);
            wS2[q1*4+3][c1] = make_float2(wv1.w, wv1.w);
        }
        __syncthreads();

        #pragma unroll
        for (int k = 0; k < 16; k++) {
            ull a01 = *(const ull*)(&embS[k][ty * 4]);      // rows ty*4, ty*4+1
            ull a23 = *(const ull*)(&embS[k][ty * 4 + 2]);  // rows ty*4+2, ty*4+3
            #pragma unroll
            for (int j = 0; j < 5; j++) {
                ull bp = *(const ull*)(&wS2[k][tx * 5 + j]);
                asm("fma.rn.f32x2 %0, %1, %2, %0;" : "+l"(acc01[j]) : "l"(a01), "l"(bp));
                asm("fma.rn.f32x2 %0, %1, %2, %0;" : "+l"(acc23[j]) : "l"(a23), "l"(bp));
            }
        }
    }

    // unpack pairs -> accv[row][col]
    float accv[4][5];
    #pragma unroll
    for (int j = 0; j < 5; j++) {
        accv[0][j] = lo32(acc01[j]); accv[1][j] = hi32(acc01[j]);
        accv[2][j] = lo32(acc23[j]); accv[3][j] = hi32(acc23[j]);
    }

    // epilogue: bias + activations -> scratch
    #pragma unroll
    for (int i = 0; i < 4; i++) {
        int row = rb + ty * 4 + i;
        if (row >= B) continue;
        if (tx <= 12) {
            #pragma unroll
            for (int j = 0; j < 5; j++) {
                int col = tx * 5 + j;
                float v = accv[i][j] + bias[col];
                if (col < 64) g_kbuf[(size_t)row * 64 + col] = v;
                else          g_pbuf[(size_t)row * 8 + 0]   = softplusf(v); // beta (col 64)
            }
        } else if (tx == 13) {  // cols 65..69: g, s0, s1, s2, gamma
            float vg = accv[i][0] + bias[65];
            float v0 = accv[i][1] + bias[66];
            float v1 = accv[i][2] + bias[67];
            float v2 = accv[i][3] + bias[68];
            float vG = accv[i][4] + bias[69];
            g_pbuf[(size_t)row * 8 + 1] = 1.0f / (1.0f + expf(-vg));
            float mx = fmaxf(v0, fmaxf(v1, v2));
            float e0 = expf(v0 - mx), e1 = expf(v1 - mx), e2 = expf(v2 - mx);
            float inv = 1.0f / (e0 + e1 + e2);
            g_pbuf[(size_t)row * 8 + 2] = e0 * inv;
            g_pbuf[(size_t)row * 8 + 3] = e1 * inv;
            g_pbuf[(size_t)row * 8 + 4] = e2 * inv;
            g_pbuf[(size_t)row * 8 + 5] = 1.0f + softplusf(vG);
        }
        // tx 14,15: padded cols, discard
    }
}

// ---------------------------------------------------------------------------
// Kernel 2: one CTA per batch row. 256 threads.
// ---------------------------------------------------------------------------
__global__ __launch_bounds__(256) void ntm_addr_kernel(
    const float* __restrict__ memory, const float* __restrict__ w_prev,
    float* __restrict__ out_r, float* __restrict__ out_w)
{
    __shared__ __align__(16) float sM[128 * 66];  // memory tile, row stride 66
    __shared__ __align__(16) float sK[64];
    __shared__ float sWp[128];
    __shared__ float sWg[128];
    __shared__ float sRed[8];
    __shared__ float sPar[256];
    __shared__ float sP[6];
    __shared__ float sInvK;

    const int t = threadIdx.x;
    const int b = blockIdx.x;

    // --- stage memory tile (32 KB), coalesced float2, front-batched (MLP=16) ---
    const float2* gm = reinterpret_cast<const float2*>(memory + (size_t)b * 8192);
    float2 stg[16];
    #pragma unroll
    for (int it = 0; it < 16; it++) stg[it] = gm[t + it * 256];
    #pragma unroll
    for (int it = 0; it < 16; it++) {
        int i = t + it * 256;               // 0..4095 float2 elements
        int n = i >> 5, jm = i & 31;        // 32 float2 per row
        *reinterpret_cast<float2*>(&sM[n * 66 + jm * 2]) = stg[it];
    }
    if (t < 64)  sK[t]  = g_kbuf[(size_t)b * 64 + t];
    if (t >= 64 && t < 192) sWp[t - 64] = w_prev[(size_t)b * 128 + (t - 64)];
    if (t >= 192 && t < 198) sP[t - 192] = g_pbuf[(size_t)b * 8 + (t - 192)];
    __syncthreads();

    // --- ||k|| by warp 7 (overlaps with pass 1) ---
    if (t >= 224) {
        int lane = t - 224;
        float v = sK[lane] * sK[lane] + sK[lane + 32] * sK[lane + 32];
        #pragma unroll
        for (int off = 16; off; off >>= 1) v += __shfl_xor_sync(0xffffffffu, v, off);
        if (lane == 0) sInvK = rsqrtf(v);
    }

    // --- pass 1: dot(mem_n, k), ||mem_n||^2, thread-per-row ---
    float dotv = 0.0f, ssv = 0.0f;
    if (t < 128) {
        const float2* k2 = reinterpret_cast<const float2*>(sK);
        const float2* m2 = reinterpret_cast<const float2*>(&sM[t * 66]);
        #pragma unroll
        for (int j = 0; j < 32; j++) {
            float2 mv = m2[j];
            float2 kv = k2[j];
            dotv = fmaf(mv.x, kv.x, dotv);
            dotv = fmaf(mv.y, kv.y, dotv);
            ssv  = fmaf(mv.x, mv.x, ssv);
            ssv  = fmaf(mv.y, mv.y, ssv);
        }
    }
    __syncthreads();  // sInvK visible

    const float beta  = sP[0], gg = sP[1];
    const float s0 = sP[2], s1 = sP[3], s2 = sP[4], gamma = sP[5];
    const int wid = t >> 5, lane = t & 31;

    float logit = 0.0f;
    if (t < 128) {
        float cosv = dotv * rsqrtf(ssv) * sInvK;
        logit = beta * cosv;
        float m = logit;
        #pragma unroll
        for (int off = 16; off; off >>= 1) m = fmaxf(m, __shfl_xor_sync(0xffffffffu, m, off));
        if (lane == 0) sRed[wid] = m;
    }
    __syncthreads();
    float gmax = fmaxf(fmaxf(sRed[0], sRed[1]), fmaxf(sRed[2], sRed[3]));

    float e = 0.0f;
    if (t < 128) {
        e = expf(logit - gmax);
        float s = e;
        #pragma unroll
        for (int off = 16; off; off >>= 1) s += __shfl_xor_sync(0xffffffffu, s, off);
        if (lane == 0) sRed[4 + wid] = s;
    }
    __syncthreads();
    float esum = sRed[4] + sRed[5] + sRed[6] + sRed[7];

    float wg = 0.0f;
    if (t < 128) {
        float wc = e / esum;
        wg = gg * wc + (1.0f - gg) * sWp[t];
        sWg[t] = wg;
    }
    __syncthreads();

    float wsp = 0.0f;
    if (t < 128) {
        float wsv = s0 * sWg[(t + 127) & 127] + s1 * wg + s2 * sWg[(t + 1) & 127];
        wsp = powf(wsv, gamma);
        float s = wsp;
        #pragma unroll
        for (int off = 16; off; off >>= 1) s += __shfl_xor_sync(0xffffffffu, s, off);
        if (lane == 0) sRed[wid] = s;
    }
    __syncthreads();
    float tot = sRed[0] + sRed[1] + sRed[2] + sRed[3] + 1e-16f;

    if (t < 128) {
        float w = wsp / tot;
        out_w[(size_t)b * 128 + t] = w;
        sWg[t] = w;  // final weights for pass 2
    }
    __syncthreads();

    // --- pass 2: r_m = sum_n w[n] * mem[n][m], from SMEM tile ---
    {
        int m = t & 63, q = t >> 6;  // 4 groups of 32 rows
        float acc = 0.0f;
        #pragma unroll
        for (int k = 0; k < 32; k++) {
            int n = q * 32 + k;
            acc = fmaf(sWg[n], sM[n * 66 + m], acc);
        }
        sPar[t] = acc;  // t == q*64 + m
    }
    __syncthreads();
    if (t < 64) {
        float r = sPar[t] + sPar[64 + t] + sPar[128 + t] + sPar[192 + t];
        out_r[(size_t)b * 64 + t] = r;
    }
}

// ---------------------------------------------------------------------------
// Launch. Inputs (metadata order): embeddings [B,512], w_prev [B,128],
// memory [B,128,64], W [70,512], b [70]. Output: r [B,64] then w [B,128].
// ---------------------------------------------------------------------------
extern "C" void kernel_launch(void* const* d_in, const int* in_sizes, int n_in,
                              void* d_out, int out_size)
{
    const float* emb    = (const float*)d_in[0];
    const float* w_prev = (const float*)d_in[1];
    const float* memory = (const float*)d_in[2];
    const float* Wm     = (const float*)d_in[3];
    const float* bias   = (const float*)d_in[4];

    int B = in_sizes[1] / 128;  // w_prev is [B,128]
    if (B > MAXB) B = MAXB;

    float* out   = (float*)d_out;
    float* out_r = out;
    float* out_w = out + (size_t)B * 64;

    int gemm_blocks = (B + 63) / 64;
    ntm_gemm_kernel<<<gemm_blocks, 256>>>(emb, Wm, bias, B);
    ntm_addr_kernel<<<B, 256>>>(memory, w_prev, out_r, out_w);
}

// round 3
// speedup vs baseline: 1.2116x; 1.2116x over previous
#include <cuda_runtime.h>
#include <math.h>

// ---------------------------------------------------------------------------
// NTM read head, B=16384, CTRL=512, N=128, M=64, 70 controller outputs.
// Kernel 1: o = emb @ W^T + b (fp32 GEMM, f32x2 packed FMA, 128-thr CTAs).
// Kernel 2: per-batch addressing + read, memory tile REGISTER-resident
//           (one HBM read, no SMEM round-trip of the 32KB tile).
// ---------------------------------------------------------------------------

#define MAXB 16384
typedef unsigned long long ull;

__device__ float g_kbuf[MAXB * 64];  // k vectors
__device__ float g_pbuf[MAXB * 8];   // beta, g, s0, s1, s2, gamma

__device__ __forceinline__ float softplusf(float x) {
    return (x > 20.0f) ? x : log1pf(expf(x));
}
__device__ __forceinline__ float lo32(ull v) {
    return __uint_as_float((unsigned)(v & 0xffffffffu));
}
__device__ __forceinline__ float hi32(ull v) {
    return __uint_as_float((unsigned)(v >> 32));
}

// ---------------------------------------------------------------------------
// Kernel 1: GEMM [B,512] x [512,70]^T. BM=64, BN=80(70 pad), BK=16.
// 128 threads: tx=t&15 (5 cols each), ty=t>>4 (8 rows each).
// Rows paired in f32x2; B duplicated {w,w}. 9 LDS.64 + 20 FFMA2 per k.
// ---------------------------------------------------------------------------
__global__ __launch_bounds__(128) void ntm_gemm_kernel(
    const float* __restrict__ emb, const float* __restrict__ Wm,
    const float* __restrict__ bias, int B)
{
    __shared__ __align__(16) float  embS[16][66];   // [k][row]
    __shared__ __align__(16) float2 wS2[16][81];    // [k][col] {w,w}, odd stride

    const int t  = threadIdx.x;
    const int tx = t & 15;     // cols tx*5 .. tx*5+4
    const int ty = t >> 4;     // rows ty*8 .. ty*8+7 (4 row-pairs)
    const int rb = blockIdx.x * 64;

    ull acc[4][5];             // [row-pair u][col j]
    #pragma unroll
    for (int u = 0; u < 4; u++)
        #pragma unroll
        for (int j = 0; j < 5; j++) acc[u][j] = 0ull;

    // emb loader: 256 float4 per tile, 2 per thread
    const int er0 = t >> 2,           ekq = t & 3;       // row 0..31
    const int er1 = (t + 128) >> 2;                      // row 32..63
    const int ger0 = (rb + er0 < B) ? rb + er0 : B - 1;
    const int ger1 = (rb + er1 < B) ? rb + er1 : B - 1;
    // W loader: 320 float4 per tile, up to 3 per thread
    const int c0 = t >> 2;            // 0..31
    const int c1 = (t + 128) >> 2;    // 32..63
    const int c2 = (t + 256) >> 2;    // 64..79 (only t<64)
    const bool has2 = (t < 64);

    for (int kk = 0; kk < 512; kk += 16) {
        float4 ev0 = *(const float4*)(emb + (size_t)ger0 * 512 + kk + ekq * 4);
        float4 ev1 = *(const float4*)(emb + (size_t)ger1 * 512 + kk + ekq * 4);
        float4 wv0 = *(const float4*)(Wm + (size_t)c0 * 512 + kk + ekq * 4);
        float4 wv1 = *(const float4*)(Wm + (size_t)c1 * 512 + kk + ekq * 4);
        float4 wv2 = make_float4(0.f, 0.f, 0.f, 0.f);
        if (has2 && c2 < 70) wv2 = *(const float4*)(Wm + (size_t)c2 * 512 + kk + ekq * 4);

        __syncthreads();  // previous tile's smem reads done

        embS[ekq*4+0][er0] = ev0.x; embS[ekq*4+1][er0] = ev0.y;
        embS[ekq*4+2][er0] = ev0.z; embS[ekq*4+3][er0] = ev0.w;
        embS[ekq*4+0][er1] = ev1.x; embS[ekq*4+1][er1] = ev1.y;
        embS[ekq*4+2][er1] = ev1.z; embS[ekq*4+3][er1] = ev1.w;
        wS2[ekq*4+0][c0] = make_float2(wv0.x, wv0.x);
        wS2[ekq*4+1][c0] = make_float2(wv0.y, wv0.y);
        wS2[ekq*4+2][c0] = make_float2(wv0.z, wv0.z);
        wS2[ekq*4+3][c0] = make_float2(wv0.w, wv0.w);
        wS2[ekq*4+0][c1] = make_float2(wv1.x, wv1.x);
        wS2[ekq*4+1][c1] = make_float2(wv1.y, wv1.y);
        wS2[ekq*4+2][c1] = make_float2(wv1.z, wv1.z);
        wS2[ekq*4+3][c1] = make_float2(wv1.w, wv1.w);
        if (has2) {
            wS2[ekq*4+0][c2] = make_float2(wv2.x, wv2.x);
            wS2[ekq*4+1][c2] = make_float2(wv2.y, wv2.y);
            wS2[ekq*4+2][c2] = make_float2(wv2.z, wv2.z);
            wS2[ekq*4+3][c2] = make_float2(wv2.w, wv2.w);
        }
        __syncthreads();

        #pragma unroll
        for (int k = 0; k < 16; k++) {
            ull a0 = *(const ull*)(&embS[k][ty * 8 + 0]);
            ull a1 = *(const ull*)(&embS[k][ty * 8 + 2]);
            ull a2 = *(const ull*)(&embS[k][ty * 8 + 4]);
            ull a3 = *(const ull*)(&embS[k][ty * 8 + 6]);
            #pragma unroll
            for (int j = 0; j < 5; j++) {
                ull bp = *(const ull*)(&wS2[k][tx * 5 + j]);
                asm("fma.rn.f32x2 %0, %1, %2, %0;" : "+l"(acc[0][j]) : "l"(a0), "l"(bp));
                asm("fma.rn.f32x2 %0, %1, %2, %0;" : "+l"(acc[1][j]) : "l"(a1), "l"(bp));
                asm("fma.rn.f32x2 %0, %1, %2, %0;" : "+l"(acc[2][j]) : "l"(a2), "l"(bp));
                asm("fma.rn.f32x2 %0, %1, %2, %0;" : "+l"(acc[3][j]) : "l"(a3), "l"(bp));
            }
        }
    }

    // epilogue: 8 rows x 5 cols per thread
    float bj[5];
    if (tx <= 13) {
        #pragma unroll
        for (int j = 0; j < 5; j++) bj[j] = bias[tx * 5 + j];
    }
    #pragma unroll
    for (int u = 0; u < 4; u++) {
        #pragma unroll
        for (int half = 0; half < 2; half++) {
            int row = rb + ty * 8 + u * 2 + half;
            if (row >= B) continue;
            if (tx <= 12) {
                #pragma unroll
                for (int j = 0; j < 5; j++) {
                    int col = tx * 5 + j;
                    float v = (half ? hi32(acc[u][j]) : lo32(acc[u][j])) + bj[j];
                    if (col < 64) g_kbuf[(size_t)row * 64 + col] = v;
                    else          g_pbuf[(size_t)row * 8 + 0]   = softplusf(v); // beta
                }
            } else if (tx == 13) {  // cols 65..69: g, s0, s1, s2, gamma
                float a0 = (half ? hi32(acc[u][0]) : lo32(acc[u][0])) + bj[0];
                float a1 = (half ? hi32(acc[u][1]) : lo32(acc[u][1])) + bj[1];
                float a2 = (half ? hi32(acc[u][2]) : lo32(acc[u][2])) + bj[2];
                float a3 = (half ? hi32(acc[u][3]) : lo32(acc[u][3])) + bj[3];
                float a4 = (half ? hi32(acc[u][4]) : lo32(acc[u][4])) + bj[4];
                g_pbuf[(size_t)row * 8 + 1] = 1.0f / (1.0f + expf(-a0));
                float mx = fmaxf(a1, fmaxf(a2, a3));
                float e0 = expf(a1 - mx), e1 = expf(a2 - mx), e2 = expf(a3 - mx);
                float inv = 1.0f / (e0 + e1 + e2);
                g_pbuf[(size_t)row * 8 + 2] = e0 * inv;
                g_pbuf[(size_t)row * 8 + 3] = e1 * inv;
                g_pbuf[(size_t)row * 8 + 4] = e2 * inv;
                g_pbuf[(size_t)row * 8 + 5] = 1.0f + softplusf(a4);
            }
        }
    }
}

// ---------------------------------------------------------------------------
// Kernel 2: one CTA per batch row, 256 threads, tile register-resident.
// Thread t (warp w, lane l): float4 v[q] = tile[2w + (l>>4) + 16q][4*(l&15)..]
// ---------------------------------------------------------------------------
__global__ __launch_bounds__(256) void ntm_addr_kernel(
    const float* __restrict__ memory, const float* __restrict__ w_prev,
    float* __restrict__ out_r, float* __restrict__ out_w)
{
    __shared__ float sDot[128], sSS[128], sW[128], sWt[128];
    __shared__ __align__(16) float4 sPar[8][16];
    __shared__ float sRed[8], sP[6], sKss;

    const int t = threadIdx.x;
    const int b = blockIdx.x;
    const int w = t >> 5, l = t & 31, h = l >> 4, cq = l & 15;

    // --- load tile to registers: 8 x LDG.128, fully coalesced ---
    const float4* gm4 = reinterpret_cast<const float4*>(memory + (size_t)b * 8192);
    float4 v[8];
    #pragma unroll
    for (int q = 0; q < 8; q++) v[q] = gm4[t + 256 * q];

    float4 kv = *reinterpret_cast<const float4*>(g_kbuf + (size_t)b * 64 + 4 * cq);
    float wp = 0.0f;
    if (t < 128) wp = w_prev[(size_t)b * 128 + t];
    if (t >= 128 && t < 134) sP[t - 128] = g_pbuf[(size_t)b * 8 + (t - 128)];

    // --- ||k||^2: half-warp butterfly over the 16 col-quads ---
    {
        float kss = kv.x*kv.x + kv.y*kv.y + kv.z*kv.z + kv.w*kv.w;
        #pragma unroll
        for (int off = 8; off; off >>= 1) kss += __shfl_xor_sync(0xffffffffu, kss, off);
        if (t == 0) sKss = kss;
    }

    // --- pass 1: per-row dot(mem,k) and ||mem||^2 from registers ---
    #pragma unroll
    for (int q = 0; q < 8; q++) {
        int row = 2 * w + h + 16 * q;
        float d  = v[q].x*kv.x + v[q].y*kv.y + v[q].z*kv.z + v[q].w*kv.w;
        float ss = v[q].x*v[q].x + v[q].y*v[q].y + v[q].z*v[q].z + v[q].w*v[q].w;
        #pragma unroll
        for (int off = 8; off; off >>= 1) {
            d  += __shfl_xor_sync(0xffffffffu, d,  off);
            ss += __shfl_xor_sync(0xffffffffu, ss, off);
        }
        if (cq == 0) { sDot[row] = d; sSS[row] = ss; }
    }
    __syncthreads();

    const float beta = sP[0], gg = sP[1];
    const float s0 = sP[2], s1 = sP[3], s2 = sP[4], gamma = sP[5];
    const float invk = rsqrtf(sKss);

    float logit = 0.0f, e = 0.0f, wgv = 0.0f, wsp = 0.0f;
    if (t < 128) {
        float cosv = sDot[t] * rsqrtf(sSS[t]) * invk;
        logit = beta * cosv;
        float m = logit;
        #pragma unroll
        for (int off = 16; off; off >>= 1) m = fmaxf(m, __shfl_xor_sync(0xffffffffu, m, off));
        if (l == 0) sRed[w] = m;
    }
    __syncthreads();
    float gmax = fmaxf(fmaxf(sRed[0], sRed[1]), fmaxf(sRed[2], sRed[3]));
    if (t < 128) {
        e = expf(logit - gmax);
        float s = e;
        #pragma unroll
        for (int off = 16; off; off >>= 1) s += __shfl_xor_sync(0xffffffffu, s, off);
        if (l == 0) sRed[4 + w] = s;
    }
    __syncthreads();
    float esum = sRed[4] + sRed[5] + sRed[6] + sRed[7];
    if (t < 128) {
        wgv = gg * (e / esum) + (1.0f - gg) * wp;
        sWt[t] = wgv;
    }
    __syncthreads();
    if (t < 128) {
        float wsv = s0 * sWt[(t + 127) & 127] + s1 * wgv + s2 * sWt[(t + 1) & 127];
        wsp = powf(wsv, gamma);
        float s = wsp;
        #pragma unroll
        for (int off = 16; off; off >>= 1) s += __shfl_xor_sync(0xffffffffu, s, off);
        if (l == 0) sRed[w] = s;
    }
    __syncthreads();
    float tot = sRed[0] + sRed[1] + sRed[2] + sRed[3] + 1e-16f;
    if (t < 128) {
        float wf = wsp / tot;
        sW[t] = wf;
        out_w[(size_t)b * 128 + t] = wf;
    }
    __syncthreads();

    // --- pass 2: r = w . memory, from the same registers ---
    float4 acc = make_float4(0.f, 0.f, 0.f, 0.f);
    #pragma unroll
    for (int q = 0; q < 8; q++) {
        float wf = sW[2 * w + h + 16 * q];
        acc.x = fmaf(wf, v[q].x, acc.x);
        acc.y = fmaf(wf, v[q].y, acc.y);
        acc.z = fmaf(wf, v[q].z, acc.z);
        acc.w = fmaf(wf, v[q].w, acc.w);
    }
    acc.x += __shfl_xor_sync(0xffffffffu, acc.x, 16);
    acc.y += __shfl_xor_sync(0xffffffffu, acc.y, 16);
    acc.z += __shfl_xor_sync(0xffffffffu, acc.z, 16);
    acc.w += __shfl_xor_sync(0xffffffffu, acc.w, 16);
    if (l < 16) sPar[w][l] = acc;
    __syncthreads();
    if (t < 64) {
        const float* pf = (const float*)sPar;
        float r = 0.0f;
        #pragma unroll
        for (int ww = 0; ww < 8; ww++) r += pf[ww * 64 + t];
        out_r[(size_t)b * 64 + t] = r;
    }
}

// ---------------------------------------------------------------------------
extern "C" void kernel_launch(void* const* d_in, const int* in_sizes, int n_in,
                              void* d_out, int out_size)
{
    const float* emb    = (const float*)d_in[0];
    const float* w_prev = (const float*)d_in[1];
    const float* memory = (const float*)d_in[2];
    const float* Wm     = (const float*)d_in[3];
    const float* bias   = (const float*)d_in[4];

    int B = in_sizes[1] / 128;
    if (B > MAXB) B = MAXB;

    float* out   = (float*)d_out;
    float* out_r = out;
    float* out_w = out + (size_t)B * 64;

    int gemm_blocks = (B + 63) / 64;
    ntm_gemm_kernel<<<gemm_blocks, 128>>>(emb, Wm, bias, B);
    ntm_addr_kernel<<<B, 256>>>(memory, w_prev, out_r, out_w);
}